// round 3
// baseline (speedup 1.0000x reference)
#include <cuda_runtime.h>
#include <cstdint>

#define THREADS 256
#define MTILE 128
#define NTILE 256
#define KTILE 32
#define STAGES 4
#define STAGE_BYTES 49152          // A 16KB + B 32KB
#define SMEM_BYTES (STAGES * STAGE_BYTES)

// 16 MB scratch for h^T [512][8192] (tf32-rounded, bias added)
static __device__ float g_hT[512u * 8192u];

// XOR swizzle: 16B chunk index (bits[6:4]) ^= row%8 (bits[9:7])
#define SWZ(o) ((o) ^ (((o) >> 3) & 0x70))

__device__ __forceinline__ uint32_t smem_u32(const void* p){
    uint32_t a;
    asm("{ .reg .u64 t; cvta.to.shared.u64 t, %1; cvt.u32.u64 %0, t; }" : "=r"(a) : "l"(p));
    return a;
}
__device__ __forceinline__ void cp_async16(uint32_t dst, const void* src){
    asm volatile("cp.async.cg.shared.global [%0], [%1], 16;" :: "r"(dst), "l"(src) : "memory");
}
__device__ __forceinline__ void cp_commit(){ asm volatile("cp.async.commit_group;" ::: "memory"); }
template<int N> __device__ __forceinline__ void cp_wait(){
    asm volatile("cp.async.wait_group %0;" :: "n"(N) : "memory");
}
__device__ __forceinline__ uint32_t cvt_tf32(uint32_t bits){
    uint32_t r;
    asm("cvt.rna.tf32.f32 %0, %1;" : "=r"(r) : "f"(__uint_as_float(bits)));
    return r;
}
__device__ __forceinline__ float tf32_rna_f(float x){
    uint32_t y; asm("cvt.rna.tf32.f32 %0, %1;" : "=r"(y) : "f"(x));
    return __uint_as_float(y);
}
__device__ __forceinline__ void ldsm4(uint32_t& r0, uint32_t& r1, uint32_t& r2, uint32_t& r3,
                                      uint32_t addr){
    asm volatile("ldmatrix.sync.aligned.m8n8.x4.shared.b16 {%0,%1,%2,%3}, [%4];"
                 : "=r"(r0), "=r"(r1), "=r"(r2), "=r"(r3) : "r"(addr));
}
__device__ __forceinline__ void mma_tf32(float* c, const uint32_t* a, const uint32_t* b){
    asm volatile(
        "mma.sync.aligned.m16n8k8.row.col.f32.tf32.tf32.f32 "
        "{%0,%1,%2,%3}, {%4,%5,%6,%7}, {%8,%9}, {%0,%1,%2,%3};"
        : "+f"(c[0]), "+f"(c[1]), "+f"(c[2]), "+f"(c[3])
        : "r"(a[0]), "r"(a[1]), "r"(a[2]), "r"(a[3]), "r"(b[0]), "r"(b[1]));
}

// D[m][n] = sum_k A[m][k]*B[n][k]  (fp32 K-major; A rna-rounded to tf32 on fragments,
// B rounded iff CVT_B — GEMM2 consumes pre-rounded hT so CVT_B=false there).
// EPI_BIAS_ROUND: C = tf32_rna(D + bias[m]); else C = D.
template<bool EPI_BIAS_ROUND, bool CVT_B>
__global__ void __launch_bounds__(THREADS, 1)
gemm_tf32(const float* __restrict__ A, const float* __restrict__ B,
          const float* __restrict__ bias, float* __restrict__ C,
          int ldA, int ldB, int ldC, int kiters)
{
    extern __shared__ char smem[];
    const uint32_t sb = smem_u32(smem);
    const int tid  = threadIdx.x;
    const int wid  = tid >> 5;
    const int lane = tid & 31;
    const int warp_m = wid & 1;       // 2 M-groups of 64
    const int warp_n = wid >> 1;      // 4 N-groups of 64
    const long m0 = (long)blockIdx.y * MTILE;
    const long n0 = (long)blockIdx.x * NTILE;

    float acc[4][8][4];
    #pragma unroll
    for (int i = 0; i < 4; i++)
        #pragma unroll
        for (int j = 0; j < 8; j++)
            #pragma unroll
            for (int k = 0; k < 4; k++) acc[i][j][k] = 0.0f;

    // producer geometry: thread -> (row, 16B chunk)
    const int prow = tid >> 3;
    const int pc   = (tid & 7) * 16;

    auto copy_stage = [&](int i, int s){
        const long k0 = (long)i * KTILE;
        const uint32_t base = sb + (uint32_t)s * STAGE_BYTES;
        #pragma unroll
        for (int r = 0; r < 4; r++){            // A: 128 rows
            const int row = prow + r * 32;
            cp_async16(base + SWZ(row * 128 + pc),
                       A + (m0 + row) * (long)ldA + k0 + (pc >> 2));
        }
        #pragma unroll
        for (int r = 0; r < 8; r++){            // B: 256 rows
            const int row = prow + r * 32;
            cp_async16(base + 16384u + SWZ(row * 128 + pc),
                       B + (n0 + row) * (long)ldB + k0 + (pc >> 2));
        }
    };

    // ldmatrix per-lane geometry (identical to validated R2 layout)
    const int rA  = (lane & 7) + ((lane >> 3) & 1) * 8;
    const int cbA = ((lane >> 4) & 1) * 16;
    const int rB  = (lane & 7) + ((lane >> 4) & 1) * 8;
    const int cbB = ((lane >> 3) & 1) * 16;

    uint32_t aoff[4], asw[4], boff[4], bsw[4];
    #pragma unroll
    for (int mt = 0; mt < 4; mt++){
        const int row = warp_m * 64 + mt * 16 + rA;
        aoff[mt] = (uint32_t)(row * 128);
        asw[mt]  = (uint32_t)((row & 7) * 16);
    }
    #pragma unroll
    for (int p = 0; p < 4; p++){
        const int row = warp_n * 64 + p * 16 + rB;
        boff[p] = (uint32_t)(row * 128);
        bsw[p]  = (uint32_t)((row & 7) * 16);
    }

    auto load_frags = [&](uint32_t baseA, uint32_t baseB, int ks,
                          uint32_t* a, uint32_t* b){
        const uint32_t kc = (uint32_t)(ks * 32);
        #pragma unroll
        for (int mt = 0; mt < 4; mt++)
            ldsm4(a[mt*4+0], a[mt*4+1], a[mt*4+2], a[mt*4+3],
                  baseA + aoff[mt] + ((kc + (uint32_t)cbA) ^ asw[mt]));
        #pragma unroll
        for (int p = 0; p < 4; p++)
            ldsm4(b[p*4+0], b[p*4+1], b[p*4+2], b[p*4+3],
                  baseB + boff[p] + ((kc + (uint32_t)cbB) ^ bsw[p]));
    };

    auto compute = [&](int s){
        const uint32_t baseA = sb + (uint32_t)s * STAGE_BYTES;
        const uint32_t baseB = baseA + 16384u;
        uint32_t a[2][16], b[2][16];
        load_frags(baseA, baseB, 0, a[0], b[0]);
        #pragma unroll
        for (int ks = 0; ks < 4; ks++){
            const int cur = ks & 1;
            if (ks < 3) load_frags(baseA, baseB, ks + 1, a[cur ^ 1], b[cur ^ 1]);
            #pragma unroll
            for (int j = 0; j < 16; j++) a[cur][j] = cvt_tf32(a[cur][j]);
            if (CVT_B){
                #pragma unroll
                for (int j = 0; j < 16; j++) b[cur][j] = cvt_tf32(b[cur][j]);
            }
            #pragma unroll
            for (int mt = 0; mt < 4; mt++)
                #pragma unroll
                for (int nt = 0; nt < 8; nt++)
                    mma_tf32(acc[mt][nt], &a[cur][mt * 4],
                             &b[cur][(nt >> 1) * 4 + (nt & 1) * 2]);
        }
    };

    // 4-stage pipeline, always-commit (empty groups keep the count uniform)
    copy_stage(0, 0); cp_commit();
    copy_stage(1, 1); cp_commit();
    copy_stage(2, 2); cp_commit();

    for (int i = 0; i < kiters; i++){
        cp_wait<2>();                 // stage i guaranteed arrived
        __syncthreads();              // all warps done with stage (i-1)&3
        if (i + 3 < kiters) copy_stage(i + 3, (i + 3) & 3);
        cp_commit();
        compute(i & 3);
    }

    // epilogue
    const int gid = lane >> 2, tig = lane & 3;
    #pragma unroll
    for (int mt = 0; mt < 4; mt++){
        const long r0 = m0 + warp_m * 64 + mt * 16 + gid;
        const long r1 = r0 + 8;
        float bv0 = 0.0f, bv1 = 0.0f;
        if (EPI_BIAS_ROUND){ bv0 = __ldg(bias + r0); bv1 = __ldg(bias + r1); }
        #pragma unroll
        for (int nt = 0; nt < 8; nt++){
            const long col = n0 + warp_n * 64 + nt * 8 + 2 * tig;
            float2 v0, v1;
            if (EPI_BIAS_ROUND){
                v0 = make_float2(tf32_rna_f(acc[mt][nt][0] + bv0),
                                 tf32_rna_f(acc[mt][nt][1] + bv0));
                v1 = make_float2(tf32_rna_f(acc[mt][nt][2] + bv1),
                                 tf32_rna_f(acc[mt][nt][3] + bv1));
            } else {
                v0 = make_float2(acc[mt][nt][0], acc[mt][nt][1]);
                v1 = make_float2(acc[mt][nt][2], acc[mt][nt][3]);
            }
            *(float2*)(C + r0 * ldC + col) = v0;
            *(float2*)(C + r1 * ldC + col) = v1;
        }
    }
}

extern "C" void kernel_launch(void* const* d_in, const int* in_sizes, int n_in,
                              void* d_out, int out_size)
{
    const float* input = (const float*)d_in[0];   // [8192, 512]
    const float* adj   = (const float*)d_in[1];   // [8192, 8192]
    const float* W     = (const float*)d_in[2];   // [512, 512]
    const float* bias  = (const float*)d_in[3];   // [512]
    float* out = (float*)d_out;                   // [8192, 512]

    cudaFuncSetAttribute(gemm_tf32<true, true>,
                         cudaFuncAttributeMaxDynamicSharedMemorySize, SMEM_BYTES);
    cudaFuncSetAttribute(gemm_tf32<false, false>,
                         cudaFuncAttributeMaxDynamicSharedMemorySize, SMEM_BYTES);

    float* hT = nullptr;
    cudaGetSymbolAddress((void**)&hT, g_hT);

    // GEMM1: hT[o][n] = tf32_rna(sum_i W[o][i]*input[n][i] + b[o])  (M=512, N=8192, K=512)
    gemm_tf32<true, true><<<dim3(8192 / NTILE, 512 / MTILE), THREADS, SMEM_BYTES>>>(
        W, input, bias, hT, 512, 512, 8192, 512 / KTILE);

    // GEMM2: out[m][o] = sum_k adj[m][k]*hT[o][k]   (M=8192, N=512, K=8192; B pre-rounded)
    gemm_tf32<false, false><<<dim3(512 / NTILE, 8192 / MTILE), THREADS, SMEM_BYTES>>>(
        adj, hT, nullptr, out, 8192, 8192, 512, 8192 / KTILE);
}

// round 4
// speedup vs baseline: 1.0889x; 1.0889x over previous
#include <cuda_runtime.h>
#include <cstdint>

#define THREADS 256
#define MTILE 128
#define NTILE 256
#define KTILE 32
#define STAGES 4
#define STAGE_BYTES 49152          // A 16KB + B 32KB
#define SMEM_BYTES (STAGES * STAGE_BYTES)

// 16 MB scratch for h^T [512][8192] (tf32-rounded, bias added)
static __device__ float g_hT[512u * 8192u];

// XOR swizzle: 16B chunk index (bits[6:4]) ^= row%8 (bits[9:7])
#define SWZ(o) ((o) ^ (((o) >> 3) & 0x70))

__device__ __forceinline__ uint32_t smem_u32(const void* p){
    uint32_t a;
    asm("{ .reg .u64 t; cvta.to.shared.u64 t, %1; cvt.u32.u64 %0, t; }" : "=r"(a) : "l"(p));
    return a;
}
__device__ __forceinline__ void cp_async16(uint32_t dst, const void* src){
    asm volatile("cp.async.cg.shared.global [%0], [%1], 16;" :: "r"(dst), "l"(src) : "memory");
}
__device__ __forceinline__ void cp_commit(){ asm volatile("cp.async.commit_group;" ::: "memory"); }
template<int N> __device__ __forceinline__ void cp_wait(){
    asm volatile("cp.async.wait_group %0;" :: "n"(N) : "memory");
}
__device__ __forceinline__ uint32_t cvt_tf32(uint32_t bits){
    uint32_t r;
    asm("cvt.rna.tf32.f32 %0, %1;" : "=r"(r) : "f"(__uint_as_float(bits)));
    return r;
}
__device__ __forceinline__ float tf32_rna_f(float x){
    uint32_t y; asm("cvt.rna.tf32.f32 %0, %1;" : "=r"(y) : "f"(x));
    return __uint_as_float(y);
}
__device__ __forceinline__ void ldsm4(uint32_t& r0, uint32_t& r1, uint32_t& r2, uint32_t& r3,
                                      uint32_t addr){
    asm volatile("ldmatrix.sync.aligned.m8n8.x4.shared.b16 {%0,%1,%2,%3}, [%4];"
                 : "=r"(r0), "=r"(r1), "=r"(r2), "=r"(r3) : "r"(addr));
}
__device__ __forceinline__ void mma_tf32(float* c, const uint32_t* a, const uint32_t* b){
    asm volatile(
        "mma.sync.aligned.m16n8k8.row.col.f32.tf32.tf32.f32 "
        "{%0,%1,%2,%3}, {%4,%5,%6,%7}, {%8,%9}, {%0,%1,%2,%3};"
        : "+f"(c[0]), "+f"(c[1]), "+f"(c[2]), "+f"(c[3])
        : "r"(a[0]), "r"(a[1]), "r"(a[2]), "r"(a[3]), "r"(b[0]), "r"(b[1]));
}

// D[m][n] = sum_k A[m][k]*B[n][k]  (fp32 K-major; A rna-rounded on fragments,
// B rounded iff CVT_B; GEMM2 consumes pre-rounded hT so CVT_B=false there).
template<bool EPI_BIAS_ROUND, bool CVT_B>
__global__ void __launch_bounds__(THREADS, 1)
gemm_tf32(const float* __restrict__ A, const float* __restrict__ B,
          const float* __restrict__ bias, float* __restrict__ C,
          int ldA, int ldB, int ldC, int kiters)
{
    extern __shared__ char smem[];
    const uint32_t sb = smem_u32(smem);
    const int tid  = threadIdx.x;
    const int wid  = tid >> 5;
    const int lane = tid & 31;
    const int warp_m = wid & 1;       // 2 M-groups of 64
    const int warp_n = wid >> 1;      // 4 N-groups of 64
    const long m0 = (long)blockIdx.y * MTILE;
    const long n0 = (long)blockIdx.x * NTILE;

    float acc[4][8][4];
    #pragma unroll
    for (int i = 0; i < 4; i++)
        #pragma unroll
        for (int j = 0; j < 8; j++)
            #pragma unroll
            for (int k = 0; k < 4; k++) acc[i][j][k] = 0.0f;

    // producer geometry: 12 chunks/thread/tile (4 A rows + 8 B rows)
    const int prow = tid >> 3;
    const int pc   = (tid & 7) * 16;

    auto copy_chunk = [&](long k0, uint32_t base, int j){
        if (j < 4){
            const int row = prow + j * 32;                       // A: 128 rows
            cp_async16(base + SWZ(row * 128 + pc),
                       A + (m0 + row) * (long)ldA + k0 + (pc >> 2));
        } else {
            const int row = prow + (j - 4) * 32;                 // B: 256 rows
            cp_async16(base + 16384u + SWZ(row * 128 + pc),
                       B + (n0 + row) * (long)ldB + k0 + (pc >> 2));
        }
    };

    // ldmatrix per-lane geometry (validated R2 layout)
    const int rA  = (lane & 7) + ((lane >> 3) & 1) * 8;
    const int cbA = ((lane >> 4) & 1) * 16;
    const int rB  = (lane & 7) + ((lane >> 4) & 1) * 8;
    const int cbB = ((lane >> 3) & 1) * 16;

    // compute one k-tile from stage s; if do_copy, interleave the 12 cp.asyncs
    // for the tile at k0n into stage base basen (3 per k-step).
    auto compute = [&](int s, long k0n, uint32_t basen, bool do_copy){
        const uint32_t baseA = sb + (uint32_t)s * STAGE_BYTES;
        const uint32_t baseB = baseA + 16384u;
        uint32_t a[2][16], b[2][16];

        // prologue frags for kstep 0
        #pragma unroll
        for (int mt = 0; mt < 4; mt++){
            const int row = warp_m * 64 + mt * 16 + rA;
            ldsm4(a[0][mt*4+0], a[0][mt*4+1], a[0][mt*4+2], a[0][mt*4+3],
                  baseA + SWZ(row * 128 + cbA));
        }
        #pragma unroll
        for (int p = 0; p < 4; p++){
            const int row = warp_n * 64 + p * 16 + rB;
            ldsm4(b[0][p*4+0], b[0][p*4+1], b[0][p*4+2], b[0][p*4+3],
                  baseB + SWZ(row * 128 + cbB));
        }

        #pragma unroll
        for (int ks = 0; ks < 4; ks++){
            const int cur = ks & 1;
            const int nxt = cur ^ 1;
            const int kcn = (ks + 1) * 32;

            // B cvts for this k-step must precede the first MMA group
            if (CVT_B){
                #pragma unroll
                for (int j = 0; j < 16; j++) b[cur][j] = cvt_tf32(b[cur][j]);
            }

            #pragma unroll
            for (int mt = 0; mt < 4; mt++){
                // interleave: prefetch frags of kstep ks+1 inside the MMA stream
                if (ks < 3){
                    const int rowA = warp_m * 64 + mt * 16 + rA;
                    ldsm4(a[nxt][mt*4+0], a[nxt][mt*4+1], a[nxt][mt*4+2], a[nxt][mt*4+3],
                          baseA + SWZ(rowA * 128 + kcn + cbA));
                    const int rowB = warp_n * 64 + mt * 16 + rB;
                    ldsm4(b[nxt][mt*4+0], b[nxt][mt*4+1], b[nxt][mt*4+2], b[nxt][mt*4+3],
                          baseB + SWZ(rowB * 128 + kcn + cbB));
                }
                #pragma unroll
                for (int j = 0; j < 4; j++) a[cur][mt*4+j] = cvt_tf32(a[cur][mt*4+j]);
                #pragma unroll
                for (int nt = 0; nt < 8; nt++)
                    mma_tf32(acc[mt][nt], &a[cur][mt * 4],
                             &b[cur][(nt >> 1) * 4 + (nt & 1) * 2]);
            }

            // interleave: issue 3 of the 12 cp.async chunks for tile i+3
            if (do_copy){
                copy_chunk(k0n, basen, 3 * ks + 0);
                copy_chunk(k0n, basen, 3 * ks + 1);
                copy_chunk(k0n, basen, 3 * ks + 2);
            }
        }
    };

    // prologue: fill stages 0..2
    #pragma unroll
    for (int s = 0; s < 3; s++){
        for (int j = 0; j < 12; j++) copy_chunk((long)s * KTILE, sb + (uint32_t)s * STAGE_BYTES, j);
        cp_commit();
    }

    for (int i = 0; i < kiters; i++){
        cp_wait<2>();                 // stage i arrived
        __syncthreads();              // everyone done reading stage (i-1)&3
        const bool dc = (i + 3 < kiters);
        compute(i & 3, (long)(i + 3) * KTILE,
                sb + (uint32_t)((i + 3) & 3) * STAGE_BYTES, dc);
        cp_commit();
    }

    // epilogue
    const int gid = lane >> 2, tig = lane & 3;
    #pragma unroll
    for (int mt = 0; mt < 4; mt++){
        const long r0 = m0 + warp_m * 64 + mt * 16 + gid;
        const long r1 = r0 + 8;
        float bv0 = 0.0f, bv1 = 0.0f;
        if (EPI_BIAS_ROUND){ bv0 = __ldg(bias + r0); bv1 = __ldg(bias + r1); }
        #pragma unroll
        for (int nt = 0; nt < 8; nt++){
            const long col = n0 + warp_n * 64 + nt * 8 + 2 * tig;
            float2 v0, v1;
            if (EPI_BIAS_ROUND){
                v0 = make_float2(tf32_rna_f(acc[mt][nt][0] + bv0),
                                 tf32_rna_f(acc[mt][nt][1] + bv0));
                v1 = make_float2(tf32_rna_f(acc[mt][nt][2] + bv1),
                                 tf32_rna_f(acc[mt][nt][3] + bv1));
            } else {
                v0 = make_float2(acc[mt][nt][0], acc[mt][nt][1]);
                v1 = make_float2(acc[mt][nt][2], acc[mt][nt][3]);
            }
            *(float2*)(C + r0 * ldC + col) = v0;
            *(float2*)(C + r1 * ldC + col) = v1;
        }
    }
}

extern "C" void kernel_launch(void* const* d_in, const int* in_sizes, int n_in,
                              void* d_out, int out_size)
{
    const float* input = (const float*)d_in[0];   // [8192, 512]
    const float* adj   = (const float*)d_in[1];   // [8192, 8192]
    const float* W     = (const float*)d_in[2];   // [512, 512]
    const float* bias  = (const float*)d_in[3];   // [512]
    float* out = (float*)d_out;                   // [8192, 512]

    cudaFuncSetAttribute(gemm_tf32<true, true>,
                         cudaFuncAttributeMaxDynamicSharedMemorySize, SMEM_BYTES);
    cudaFuncSetAttribute(gemm_tf32<false, false>,
                         cudaFuncAttributeMaxDynamicSharedMemorySize, SMEM_BYTES);

    float* hT = nullptr;
    cudaGetSymbolAddress((void**)&hT, g_hT);

    // GEMM1: hT[o][n] = tf32_rna(sum_i W[o][i]*input[n][i] + b[o])  (M=512, N=8192, K=512)
    gemm_tf32<true, true><<<dim3(8192 / NTILE, 512 / MTILE), THREADS, SMEM_BYTES>>>(
        W, input, bias, hT, 512, 512, 8192, 512 / KTILE);

    // GEMM2: out[m][o] = sum_k adj[m][k]*hT[o][k]   (M=8192, N=512, K=8192; B pre-rounded)
    gemm_tf32<false, false><<<dim3(512 / NTILE, 8192 / MTILE), THREADS, SMEM_BYTES>>>(
        adj, hT, nullptr, out, 8192, 8192, 512, 8192 / KTILE);
}

// round 5
// speedup vs baseline: 1.0896x; 1.0007x over previous
#include <cuda_runtime.h>
#include <cstdint>

#define THREADS 256
#define MTILE 128
#define NTILE 256
#define KTILE 32
#define STAGES 4
#define STAGE_BYTES 49152          // A 16KB + B 32KB
#define SMEM_BYTES (STAGES * STAGE_BYTES)

// 16 MB scratch for h^T [512][8192] (tf32-rounded, bias added)
static __device__ float g_hT[512u * 8192u];

// XOR swizzle: 16B chunk index (bits[6:4]) ^= row%8 (bits[9:7])
#define SWZ(o) ((o) ^ (((o) >> 3) & 0x70))

__device__ __forceinline__ uint32_t smem_u32(const void* p){
    uint32_t a;
    asm("{ .reg .u64 t; cvta.to.shared.u64 t, %1; cvt.u32.u64 %0, t; }" : "=r"(a) : "l"(p));
    return a;
}
__device__ __forceinline__ void cp_async16(uint32_t dst, const void* src){
    asm volatile("cp.async.cg.shared.global [%0], [%1], 16;" :: "r"(dst), "l"(src) : "memory");
}
__device__ __forceinline__ void cp_commit(){ asm volatile("cp.async.commit_group;" ::: "memory"); }
template<int N> __device__ __forceinline__ void cp_wait(){
    asm volatile("cp.async.wait_group %0;" :: "n"(N) : "memory");
}
__device__ __forceinline__ uint32_t cvt_tf32(uint32_t bits){
    uint32_t r;
    asm("cvt.rna.tf32.f32 %0, %1;" : "=r"(r) : "f"(__uint_as_float(bits)));
    return r;
}
__device__ __forceinline__ float tf32_rna_f(float x){
    uint32_t y; asm("cvt.rna.tf32.f32 %0, %1;" : "=r"(y) : "f"(x));
    return __uint_as_float(y);
}
__device__ __forceinline__ void ldsm4(uint32_t& r0, uint32_t& r1, uint32_t& r2, uint32_t& r3,
                                      uint32_t addr){
    asm volatile("ldmatrix.sync.aligned.m8n8.x4.shared.b16 {%0,%1,%2,%3}, [%4];"
                 : "=r"(r0), "=r"(r1), "=r"(r2), "=r"(r3) : "r"(addr));
}
__device__ __forceinline__ void mma_tf32(float* c, const uint32_t* a, const uint32_t* b){
    asm volatile(
        "mma.sync.aligned.m16n8k8.row.col.f32.tf32.tf32.f32 "
        "{%0,%1,%2,%3}, {%4,%5,%6,%7}, {%8,%9}, {%0,%1,%2,%3};"
        : "+f"(c[0]), "+f"(c[1]), "+f"(c[2]), "+f"(c[3])
        : "r"(a[0]), "r"(a[1]), "r"(a[2]), "r"(a[3]), "r"(b[0]), "r"(b[1]));
}

// D[m][n] = sum_k A[m][k]*B[n][k]  (fp32 K-major; A rna-rounded on fragments,
// B rounded iff CVT_B; GEMM2 consumes pre-rounded hT so CVT_B=false there).
template<bool EPI_BIAS_ROUND, bool CVT_B>
__global__ void __launch_bounds__(THREADS, 1)
gemm_tf32(const float* __restrict__ A, const float* __restrict__ B,
          const float* __restrict__ bias, float* __restrict__ C,
          int ldA, int ldB, int ldC, int kiters)
{
    extern __shared__ char smem[];
    const uint32_t sb = smem_u32(smem);
    const int tid  = threadIdx.x;
    const int wid  = tid >> 5;
    const int lane = tid & 31;
    const int warp_m = wid & 1;       // 2 M-groups of 64
    const int warp_n = wid >> 1;      // 4 N-groups of 64
    const long m0 = (long)blockIdx.y * MTILE;
    const long n0 = (long)blockIdx.x * NTILE;

    float acc[4][8][4];
    #pragma unroll
    for (int i = 0; i < 4; i++)
        #pragma unroll
        for (int j = 0; j < 8; j++)
            #pragma unroll
            for (int k = 0; k < 4; k++) acc[i][j][k] = 0.0f;

    // producer geometry: 12 chunks/thread/tile (4 A rows + 8 B rows)
    const int prow = tid >> 3;
    const int pc   = (tid & 7) * 16;

    auto copy_chunk = [&](long k0, uint32_t base, int j){
        if (j < 4){
            const int row = prow + j * 32;                       // A: 128 rows
            cp_async16(base + SWZ(row * 128 + pc),
                       A + (m0 + row) * (long)ldA + k0 + (pc >> 2));
        } else {
            const int row = prow + (j - 4) * 32;                 // B: 256 rows
            cp_async16(base + 16384u + SWZ(row * 128 + pc),
                       B + (n0 + row) * (long)ldB + k0 + (pc >> 2));
        }
    };

    // ldmatrix per-lane geometry (validated R2 layout)
    const int rA  = (lane & 7) + ((lane >> 3) & 1) * 8;
    const int cbA = ((lane >> 4) & 1) * 16;
    const int rB  = (lane & 7) + ((lane >> 4) & 1) * 8;
    const int cbB = ((lane >> 3) & 1) * 16;

    // compute one k-tile from stage s; if do_copy, interleave the 12 cp.asyncs
    // for the tile at k0n into stage base basen (3 per k-step).
    auto compute = [&](int s, long k0n, uint32_t basen, bool do_copy){
        const uint32_t baseA = sb + (uint32_t)s * STAGE_BYTES;
        const uint32_t baseB = baseA + 16384u;
        uint32_t a[2][16], b[2][16];

        // prologue frags for kstep 0
        #pragma unroll
        for (int mt = 0; mt < 4; mt++){
            const int row = warp_m * 64 + mt * 16 + rA;
            ldsm4(a[0][mt*4+0], a[0][mt*4+1], a[0][mt*4+2], a[0][mt*4+3],
                  baseA + SWZ(row * 128 + cbA));
        }
        #pragma unroll
        for (int p = 0; p < 4; p++){
            const int row = warp_n * 64 + p * 16 + rB;
            ldsm4(b[0][p*4+0], b[0][p*4+1], b[0][p*4+2], b[0][p*4+3],
                  baseB + SWZ(row * 128 + cbB));
        }

        #pragma unroll
        for (int ks = 0; ks < 4; ks++){
            const int cur = ks & 1;
            const int nxt = cur ^ 1;
            const int kcn = (ks + 1) * 32;

            // B cvts for this k-step must precede the first MMA group
            if (CVT_B){
                #pragma unroll
                for (int j = 0; j < 16; j++) b[cur][j] = cvt_tf32(b[cur][j]);
            }

            #pragma unroll
            for (int mt = 0; mt < 4; mt++){
                // interleave: prefetch frags of kstep ks+1 inside the MMA stream
                if (ks < 3){
                    const int rowA = warp_m * 64 + mt * 16 + rA;
                    ldsm4(a[nxt][mt*4+0], a[nxt][mt*4+1], a[nxt][mt*4+2], a[nxt][mt*4+3],
                          baseA + SWZ(rowA * 128 + kcn + cbA));
                    const int rowB = warp_n * 64 + mt * 16 + rB;
                    ldsm4(b[nxt][mt*4+0], b[nxt][mt*4+1], b[nxt][mt*4+2], b[nxt][mt*4+3],
                          baseB + SWZ(rowB * 128 + kcn + cbB));
                }
                #pragma unroll
                for (int j = 0; j < 4; j++) a[cur][mt*4+j] = cvt_tf32(a[cur][mt*4+j]);
                #pragma unroll
                for (int nt = 0; nt < 8; nt++)
                    mma_tf32(acc[mt][nt], &a[cur][mt * 4],
                             &b[cur][(nt >> 1) * 4 + (nt & 1) * 2]);
            }

            // interleave: issue 3 of the 12 cp.async chunks for tile i+3
            if (do_copy){
                copy_chunk(k0n, basen, 3 * ks + 0);
                copy_chunk(k0n, basen, 3 * ks + 1);
                copy_chunk(k0n, basen, 3 * ks + 2);
            }
        }
    };

    // prologue: fill stages 0..2
    #pragma unroll
    for (int s = 0; s < 3; s++){
        for (int j = 0; j < 12; j++) copy_chunk((long)s * KTILE, sb + (uint32_t)s * STAGE_BYTES, j);
        cp_commit();
    }

    for (int i = 0; i < kiters; i++){
        cp_wait<2>();                 // stage i arrived
        __syncthreads();              // everyone done reading stage (i-1)&3
        const bool dc = (i + 3 < kiters);
        compute(i & 3, (long)(i + 3) * KTILE,
                sb + (uint32_t)((i + 3) & 3) * STAGE_BYTES, dc);
        cp_commit();
    }

    // epilogue
    const int gid = lane >> 2, tig = lane & 3;
    #pragma unroll
    for (int mt = 0; mt < 4; mt++){
        const long r0 = m0 + warp_m * 64 + mt * 16 + gid;
        const long r1 = r0 + 8;
        float bv0 = 0.0f, bv1 = 0.0f;
        if (EPI_BIAS_ROUND){ bv0 = __ldg(bias + r0); bv1 = __ldg(bias + r1); }
        #pragma unroll
        for (int nt = 0; nt < 8; nt++){
            const long col = n0 + warp_n * 64 + nt * 8 + 2 * tig;
            float2 v0, v1;
            if (EPI_BIAS_ROUND){
                v0 = make_float2(tf32_rna_f(acc[mt][nt][0] + bv0),
                                 tf32_rna_f(acc[mt][nt][1] + bv0));
                v1 = make_float2(tf32_rna_f(acc[mt][nt][2] + bv1),
                                 tf32_rna_f(acc[mt][nt][3] + bv1));
            } else {
                v0 = make_float2(acc[mt][nt][0], acc[mt][nt][1]);
                v1 = make_float2(acc[mt][nt][2], acc[mt][nt][3]);
            }
            *(float2*)(C + r0 * ldC + col) = v0;
            *(float2*)(C + r1 * ldC + col) = v1;
        }
    }
}

extern "C" void kernel_launch(void* const* d_in, const int* in_sizes, int n_in,
                              void* d_out, int out_size)
{
    const float* input = (const float*)d_in[0];   // [8192, 512]
    const float* adj   = (const float*)d_in[1];   // [8192, 8192]
    const float* W     = (const float*)d_in[2];   // [512, 512]
    const float* bias  = (const float*)d_in[3];   // [512]
    float* out = (float*)d_out;                   // [8192, 512]

    cudaFuncSetAttribute(gemm_tf32<true, true>,
                         cudaFuncAttributeMaxDynamicSharedMemorySize, SMEM_BYTES);
    cudaFuncSetAttribute(gemm_tf32<false, false>,
                         cudaFuncAttributeMaxDynamicSharedMemorySize, SMEM_BYTES);

    float* hT = nullptr;
    cudaGetSymbolAddress((void**)&hT, g_hT);

    // GEMM1: hT[o][n] = tf32_rna(sum_i W[o][i]*input[n][i] + b[o])  (M=512, N=8192, K=512)
    gemm_tf32<true, true><<<dim3(8192 / NTILE, 512 / MTILE), THREADS, SMEM_BYTES>>>(
        W, input, bias, hT, 512, 512, 8192, 512 / KTILE);

    // GEMM2: out[m][o] = sum_k adj[m][k]*hT[o][k]   (M=8192, N=512, K=8192; B pre-rounded)
    gemm_tf32<false, false><<<dim3(512 / NTILE, 8192 / MTILE), THREADS, SMEM_BYTES>>>(
        adj, hT, nullptr, out, 8192, 8192, 512, 8192 / KTILE);
}